// round 1
// baseline (speedup 1.0000x reference)
#include <cuda_runtime.h>
#include <math.h>

#define B 32
#define H 512
#define W 512
#define KS 31
#define PAD 15
#define IMG (H * W)

// Scratch: vertical box-sum of target (32 MB) + per-batch accumulators.
__device__ float g_vsum[B * IMG];
__device__ float g_acc[B * 4];   // [wsum, wbce_num, inter, union] per batch

// ---------------------------------------------------------------------------
// K1: vertical sliding-window sum over rows (window 31, zero pad 15).
// One block per image, one thread per column. Also zeroes accumulators.
// ---------------------------------------------------------------------------
__global__ void vert_sum_kernel(const float* __restrict__ target) {
    const int b = blockIdx.x;
    const int w = threadIdx.x;

    if (w < 4) g_acc[b * 4 + w] = 0.0f;

    const float* t = target + b * IMG;
    float* v = g_vsum + b * IMG;

    float sum = 0.0f;
    #pragma unroll
    for (int h = 0; h < PAD; ++h) sum += t[h * W + w];

    for (int h = 0; h < H; ++h) {
        const int ha = h + PAD;
        if (ha < H) sum += t[ha * W + w];
        v[h * W + w] = sum;
        const int hr = h - PAD;
        if (hr >= 0) sum -= t[hr * W + w];
    }
}

__inline__ __device__ float warp_reduce(float v) {
    #pragma unroll
    for (int o = 16; o > 0; o >>= 1) v += __shfl_down_sync(0xffffffffu, v, o);
    return v;
}

// ---------------------------------------------------------------------------
// K2: horizontal box sum (from smem row) + fused loss elementwise + reduction.
// grid = (H, B), block = 512 threads (one per column).
// ---------------------------------------------------------------------------
__global__ void fused_row_kernel(const float* __restrict__ pred,
                                 const float* __restrict__ target) {
    const int row = blockIdx.x;
    const int b   = blockIdx.y;
    const int w   = threadIdx.x;

    __shared__ float srow[W + 2 * PAD];

    const float* vrow = g_vsum + b * IMG + row * W;
    srow[w + PAD] = vrow[w];
    if (w < PAD) {
        srow[w] = 0.0f;
        srow[W + PAD + w] = 0.0f;
    }
    __syncthreads();

    // 31-tap horizontal sum from shared memory
    float hsum = 0.0f;
    #pragma unroll
    for (int i = 0; i < KS; ++i) hsum += srow[w + i];
    const float box = hsum * (1.0f / (KS * KS));

    const int idx = b * IMG + row * W + w;
    const float x  = pred[idx];
    const float tg = target[idx];

    const float weit = 1.0f + 5.0f * fabsf(box - tg);

    // stable BCE with logits
    const float wbce_el = fmaxf(x, 0.0f) - x * tg + log1pf(expf(-fabsf(x)));

    const float p = 1.0f / (1.0f + expf(-x));

    float vals[4];
    vals[0] = weit;                 // wsum
    vals[1] = weit * wbce_el;       // wbce numerator
    vals[2] = p * tg * weit;        // inter
    vals[3] = (p + tg) * weit;      // union

    __shared__ float red[4][16];
    const int lane = w & 31;
    const int wid  = w >> 5;

    #pragma unroll
    for (int i = 0; i < 4; ++i) {
        float v = warp_reduce(vals[i]);
        if (lane == 0) red[i][wid] = v;
    }
    __syncthreads();
    if (wid == 0) {
        #pragma unroll
        for (int i = 0; i < 4; ++i) {
            float v = (lane < 16) ? red[i][lane] : 0.0f;
            v = warp_reduce(v);
            if (lane == 0) atomicAdd(&g_acc[b * 4 + i], v);
        }
    }
}

// ---------------------------------------------------------------------------
// K3: per-batch loss + mean -> scalar
// ---------------------------------------------------------------------------
__global__ void final_kernel(float* __restrict__ out) {
    const int b = threadIdx.x;   // 32 threads
    const float wsum  = g_acc[b * 4 + 0];
    const float wbce_n = g_acc[b * 4 + 1];
    const float inter = g_acc[b * 4 + 2];
    const float uni   = g_acc[b * 4 + 3];

    const float wbce = wbce_n / wsum;
    const float wiou = 1.0f - (inter + 1.0f) / (uni - inter + 1.0f);
    float loss = wbce + wiou;

    loss = warp_reduce(loss);
    if (b == 0) out[0] = loss * (1.0f / B);
}

extern "C" void kernel_launch(void* const* d_in, const int* in_sizes, int n_in,
                              void* d_out, int out_size) {
    const float* pred   = (const float*)d_in[0];
    const float* target = (const float*)d_in[1];
    float* out = (float*)d_out;

    vert_sum_kernel<<<B, W>>>(target);
    dim3 grid(H, B);
    fused_row_kernel<<<grid, W>>>(pred, target);
    final_kernel<<<1, 32>>>(out);
}

// round 2
// speedup vs baseline: 4.1079x; 4.1079x over previous
#include <cuda_runtime.h>
#include <math.h>

#define B 32
#define H 512
#define W 512
#define KS 31
#define PAD 15
#define IMG (H * W)
#define STRIPS 8
#define ROWS_PER_STRIP (H / STRIPS)   // 64

// Per-block partial sums: [b][strip][4] = {wsum, wbce_num, inter, union}
__device__ float g_part[B * STRIPS * 4];

__inline__ __device__ float warp_reduce(float v) {
    #pragma unroll
    for (int o = 16; o > 0; o >>= 1) v += __shfl_down_sync(0xffffffffu, v, o);
    return v;
}

__inline__ __device__ float warp_iscan(float v, int lane) {
    #pragma unroll
    for (int o = 1; o < 32; o <<= 1) {
        float n = __shfl_up_sync(0xffffffffu, v, o);
        if (lane >= o) v += n;
    }
    return v;
}

// ---------------------------------------------------------------------------
// Fused kernel: vertical sliding sum (registers) + horizontal sum via block
// prefix scan + elementwise loss + per-block partial reduction.
// grid = (STRIPS, B), block = 512 (one thread per column).
// ---------------------------------------------------------------------------
__global__ void __launch_bounds__(512, 2)
fused_loss_kernel(const float* __restrict__ pred,
                  const float* __restrict__ target) {
    const int strip = blockIdx.x;
    const int b     = blockIdx.y;
    const int w     = threadIdx.x;
    const int lane  = w & 31;
    const int wid   = w >> 5;
    const int r0    = strip * ROWS_PER_STRIP;

    const float* t = target + b * IMG;
    const float* pr = pred + b * IMG;

    __shared__ float s_warp[16];
    __shared__ float s_off[16];
    __shared__ float sP[W];
    __shared__ float s_red[4][16];

    // Initial vertical window: rows [r0-15, r0+14] clamped
    float sum = 0.0f;
    {
        int hlo = r0 - PAD; if (hlo < 0) hlo = 0;
        int hhi = r0 + PAD;            // exclusive: r0+14 inclusive
        if (hhi > H) hhi = H;
        for (int h = hlo; h < hhi; ++h) sum += t[h * W + w];
    }

    float addv = (r0 + PAD < H) ? t[(r0 + PAD) * W + w] : 0.0f;

    float acc0 = 0.0f, acc1 = 0.0f, acc2 = 0.0f, acc3 = 0.0f;

    for (int i = 0; i < ROWS_PER_STRIP; ++i) {
        const int r = r0 + i;
        sum += addv;                 // sum = vsum(r) = rows [r-15, r+15]
        const float v = sum;

        // prefetch loads for overlap with scan
        const float subv = (r - PAD >= 0) ? t[(r - PAD) * W + w] : 0.0f;
        addv = (r + PAD + 1 < H) ? t[(r + PAD + 1) * W + w] : 0.0f;
        const float tg = t[r * W + w];
        const float x  = pr[r * W + w];

        // ---- block inclusive prefix sum of v over 512 columns ----
        float ws = warp_iscan(v, lane);
        if (lane == 31) s_warp[wid] = ws;
        __syncthreads();
        if (wid == 0) {
            float xv = (lane < 16) ? s_warp[lane] : 0.0f;
            float xs = warp_iscan(xv, lane);
            if (lane < 16) s_off[lane] = xs - xv;   // exclusive offset
        }
        __syncthreads();
        sP[w] = ws + s_off[wid];
        __syncthreads();

        const int hi_idx = (w + PAD < W) ? (w + PAD) : (W - 1);
        const float hi = sP[hi_idx];
        const float lo = (w >= PAD + 1) ? sP[w - PAD - 1] : 0.0f;
        const float box = (hi - lo) * (1.0f / (KS * KS));

        // ---- elementwise loss ----
        const float weit = 1.0f + 5.0f * fabsf(box - tg);
        const float e    = __expf(-fabsf(x));
        const float lg   = __logf(1.0f + e);
        const float bce  = fmaxf(x, 0.0f) - x * tg + lg;
        const float inv  = __fdividef(1.0f, 1.0f + e);
        const float p    = (x >= 0.0f) ? inv : 1.0f - inv;

        acc0 += weit;
        acc1 += weit * bce;
        acc2 += p * tg * weit;
        acc3 += (p + tg) * weit;

        sum -= subv;                 // ready for next row
    }

    // ---- block reduction of 4 accumulators ----
    float vals[4] = {acc0, acc1, acc2, acc3};
    #pragma unroll
    for (int k = 0; k < 4; ++k) {
        float v = warp_reduce(vals[k]);
        if (lane == 0) s_red[k][wid] = v;
    }
    __syncthreads();
    if (wid == 0) {
        #pragma unroll
        for (int k = 0; k < 4; ++k) {
            float v = (lane < 16) ? s_red[k][lane] : 0.0f;
            v = warp_reduce(v);
            if (lane == 0) g_part[(b * STRIPS + strip) * 4 + k] = v;
        }
    }
}

// ---------------------------------------------------------------------------
// Final: reduce strips per image, compute loss, mean over batch.
// ---------------------------------------------------------------------------
__global__ void final_kernel(float* __restrict__ out) {
    const int b = threadIdx.x;   // 32 threads, one per image
    float wsum = 0.0f, wbce_n = 0.0f, inter = 0.0f, uni = 0.0f;
    #pragma unroll
    for (int s = 0; s < STRIPS; ++s) {
        const float* pp = &g_part[(b * STRIPS + s) * 4];
        wsum   += pp[0];
        wbce_n += pp[1];
        inter  += pp[2];
        uni    += pp[3];
    }
    const float wbce = wbce_n / wsum;
    const float wiou = 1.0f - (inter + 1.0f) / (uni - inter + 1.0f);
    float loss = wbce + wiou;
    loss = warp_reduce(loss);
    if (b == 0) out[0] = loss * (1.0f / B);
}

extern "C" void kernel_launch(void* const* d_in, const int* in_sizes, int n_in,
                              void* d_out, int out_size) {
    const float* pred   = (const float*)d_in[0];
    const float* target = (const float*)d_in[1];
    float* out = (float*)d_out;

    dim3 grid(STRIPS, B);
    fused_loss_kernel<<<grid, W>>>(pred, target);
    final_kernel<<<1, B>>>(out);
}

// round 3
// speedup vs baseline: 4.8261x; 1.1748x over previous
#include <cuda_runtime.h>
#include <math.h>

#define B 32
#define H 512
#define W 512
#define KS 31
#define PAD 15
#define IMG (H * W)
#define STRIPS 16
#define ROWS_PER_STRIP (H / STRIPS)   // 32
#define RB 4                          // rows per scan batch
#define GROUPS (ROWS_PER_STRIP / RB)  // 8
#define NBLOCKS (B * STRIPS)          // 512

// Per-block partials: [b][strip][4] = {wsum, wbce_num, inter, union}
__device__ float g_part[NBLOCKS * 4];
__device__ unsigned int g_ctr;        // zero-init at load; reset by last block

__inline__ __device__ float warp_reduce(float v) {
    #pragma unroll
    for (int o = 16; o > 0; o >>= 1) v += __shfl_down_sync(0xffffffffu, v, o);
    return v;
}

__inline__ __device__ float warp_iscan(float v, int lane) {
    #pragma unroll
    for (int o = 1; o < 32; o <<= 1) {
        float n = __shfl_up_sync(0xffffffffu, v, o);
        if (lane >= o) v += n;
    }
    return v;
}

__global__ void __launch_bounds__(512, 3)
fused_loss_kernel(const float* __restrict__ pred,
                  const float* __restrict__ target,
                  float* __restrict__ out) {
    const int strip = blockIdx.x;
    const int b     = blockIdx.y;
    const int w     = threadIdx.x;
    const int lane  = w & 31;
    const int wid   = w >> 5;
    const int r0    = strip * ROWS_PER_STRIP;

    const float* t  = target + b * IMG;
    const float* pr = pred + b * IMG;

    __shared__ float sP[RB][W];
    __shared__ float s_warp[RB][16];
    __shared__ float s_off[RB][16];
    __shared__ float s_red[4][16];

    // Vertical window invariant entering row r: sum = rows [r-15, r+14] (clamped)
    float sum = 0.0f;
    {
        int hlo = r0 - PAD; if (hlo < 0) hlo = 0;
        int hhi = r0 + PAD; if (hhi > H) hhi = H;   // exclusive -> r0+14 incl.
        for (int h = hlo; h < hhi; ++h) sum += t[h * W + w];
    }

    float acc0 = 0.0f, acc1 = 0.0f, acc2 = 0.0f, acc3 = 0.0f;

    for (int g = 0; g < GROUPS; ++g) {
        const int rg = r0 + g * RB;

        float vs[RB], tg[RB], x[RB];

        // vertical sliding sums for RB rows + prefetch pred/target
        #pragma unroll
        for (int j = 0; j < RB; ++j) {
            const int r = rg + j;
            const float addv = (r + PAD < H) ? t[(r + PAD) * W + w] : 0.0f;
            sum += addv;                 // rows [r-15, r+15]
            vs[j] = sum;
            const float subv = (r - PAD >= 0) ? t[(r - PAD) * W + w] : 0.0f;
            sum -= subv;                 // invariant for r+1
            tg[j] = t[r * W + w];
            x[j]  = pr[r * W + w];
        }

        // RB independent warp scans (ILP across j)
        float ws[RB];
        #pragma unroll
        for (int j = 0; j < RB; ++j) ws[j] = warp_iscan(vs[j], lane);

        if (lane == 31) {
            #pragma unroll
            for (int j = 0; j < RB; ++j) s_warp[j][wid] = ws[j];
        }
        __syncthreads();

        // warps 0..RB-1 compute the 16-wide offset scan for row j=wid (parallel)
        if (wid < RB) {
            const int j = wid;
            float v0 = (lane < 16) ? s_warp[j][lane] : 0.0f;
            float xs = warp_iscan(v0, lane);
            if (lane < 16) s_off[j][lane] = xs - v0;   // exclusive prefix
        }
        __syncthreads();

        #pragma unroll
        for (int j = 0; j < RB; ++j) sP[j][w] = ws[j] + s_off[j][wid];
        __syncthreads();

        const int hi_idx = (w + PAD < W) ? (w + PAD) : (W - 1);

        #pragma unroll
        for (int j = 0; j < RB; ++j) {
            const float hi = sP[j][hi_idx];
            const float lo = (w >= PAD + 1) ? sP[j][w - PAD - 1] : 0.0f;
            const float box = (hi - lo) * (1.0f / (KS * KS));

            const float weit = 1.0f + 5.0f * fabsf(box - tg[j]);
            const float e    = __expf(-fabsf(x[j]));
            const float lg   = __logf(1.0f + e);
            const float bce  = fmaxf(x[j], 0.0f) - x[j] * tg[j] + lg;
            const float inv  = __fdividef(1.0f, 1.0f + e);
            const float p    = (x[j] >= 0.0f) ? inv : 1.0f - inv;

            acc0 += weit;
            acc1 += weit * bce;
            acc2 += p * tg[j] * weit;
            acc3 += (p + tg[j]) * weit;
        }
        __syncthreads();   // protect sP/s_warp before next group's writes
    }

    // ---- block reduction of 4 accumulators ----
    float vals[4] = {acc0, acc1, acc2, acc3};
    #pragma unroll
    for (int k = 0; k < 4; ++k) {
        float v = warp_reduce(vals[k]);
        if (lane == 0) s_red[k][wid] = v;
    }
    __syncthreads();

    if (wid == 0) {
        float v[4];
        #pragma unroll
        for (int k = 0; k < 4; ++k) {
            float vv = (lane < 16) ? s_red[k][lane] : 0.0f;
            v[k] = warp_reduce(vv);
        }
        if (lane == 0) {
            #pragma unroll
            for (int k = 0; k < 4; ++k)
                g_part[(b * STRIPS + strip) * 4 + k] = v[k];
            __threadfence();
        }
        __syncwarp();

        // last-block-done: final reduction fused in (no 2nd kernel)
        unsigned int ticket = 0;
        if (lane == 0) ticket = atomicAdd(&g_ctr, 1u);
        ticket = __shfl_sync(0xffffffffu, ticket, 0);
        if (ticket == NBLOCKS - 1) {
            // lane = batch index
            float wsum = 0.0f, wbce_n = 0.0f, inter = 0.0f, uni = 0.0f;
            #pragma unroll
            for (int s = 0; s < STRIPS; ++s) {
                const float* pp = &g_part[(lane * STRIPS + s) * 4];
                wsum   += pp[0];
                wbce_n += pp[1];
                inter  += pp[2];
                uni    += pp[3];
            }
            const float wbce = wbce_n / wsum;
            const float wiou = 1.0f - (inter + 1.0f) / (uni - inter + 1.0f);
            float loss = warp_reduce(wbce + wiou);
            if (lane == 0) {
                out[0] = loss * (1.0f / B);
                g_ctr = 0;   // reset for next graph replay
            }
        }
    }
}

extern "C" void kernel_launch(void* const* d_in, const int* in_sizes, int n_in,
                              void* d_out, int out_size) {
    const float* pred   = (const float*)d_in[0];
    const float* target = (const float*)d_in[1];
    float* out = (float*)d_out;

    dim3 grid(STRIPS, B);
    fused_loss_kernel<<<grid, W>>>(pred, target, out);
}

// round 4
// speedup vs baseline: 6.2316x; 1.2912x over previous
#include <cuda_runtime.h>
#include <math.h>

#define B 32
#define H 512
#define W 512
#define C4 (W / 4)            // 128 float4 per row
#define KS 31
#define PAD 15
#define IMG (H * W)
#define IMG4 (H * C4)
#define STRIPS 32
#define ROWS (H / STRIPS)      // 16 rows per block
#define NBLOCKS (B * STRIPS)   // 1024

// Per-block partials: [b][strip][4] = {wsum, wbce_num, inter, union}
__device__ float g_part[NBLOCKS * 4];
__device__ unsigned int g_ctr;   // zero-init; last block resets for graph replay

__inline__ __device__ float warp_reduce(float v) {
    #pragma unroll
    for (int o = 16; o > 0; o >>= 1) v += __shfl_down_sync(0xffffffffu, v, o);
    return v;
}

__inline__ __device__ float warp_iscan(float v, int lane) {
    #pragma unroll
    for (int o = 1; o < 32; o <<= 1) {
        float n = __shfl_up_sync(0xffffffffu, v, o);
        if (lane >= o) v += n;
    }
    return v;
}

__global__ void __launch_bounds__(128, 7)
fused_loss_kernel(const float4* __restrict__ pred,
                  const float4* __restrict__ target,
                  float* __restrict__ out) {
    const int strip = blockIdx.x;
    const int b     = blockIdx.y;
    const int w     = threadIdx.x;          // float4-column index, 0..127
    const int lane  = w & 31;
    const int wid   = w >> 5;
    const int r0    = strip * ROWS;

    const float4* t = target + b * IMG4;
    const float4* p = pred   + b * IMG4;

    // sP layout: index u+4 holds P4[u], u in [-4 .. 131].
    // [0..3] = zeros (front pad), [132..135] = row total (tail pad).
    __shared__ float4 sP[2][136];
    __shared__ float  s_warp[2][4];
    __shared__ float  s_red[4][4];

    if (w < 8) sP[w >> 2][w & 3] = make_float4(0.f, 0.f, 0.f, 0.f);

    // Vertical sliding window (float4): entering row r, sum4 = rows [r-15, r+14]
    float4 sum4 = make_float4(0.f, 0.f, 0.f, 0.f);
    {
        int hlo = r0 - PAD; if (hlo < 0) hlo = 0;
        int hhi = r0 + PAD; if (hhi > H) hhi = H;
        #pragma unroll 5
        for (int h = hlo; h < hhi; ++h) {
            float4 v = t[h * C4 + w];
            sum4.x += v.x; sum4.y += v.y; sum4.z += v.z; sum4.w += v.w;
        }
    }

    float acc0 = 0.f, acc1 = 0.f, acc2 = 0.f, acc3 = 0.f;
    const float inv = 1.0f / (KS * KS);

    #pragma unroll 2
    for (int i = 0; i < ROWS; ++i) {
        const int r   = r0 + i;
        const int buf = i & 1;

        float4 addv = (r + PAD < H) ? t[(r + PAD) * C4 + w]
                                    : make_float4(0.f, 0.f, 0.f, 0.f);
        sum4.x += addv.x; sum4.y += addv.y; sum4.z += addv.z; sum4.w += addv.w;
        const float4 vs = sum4;
        float4 subv = (r - PAD >= 0) ? t[(r - PAD) * C4 + w]
                                     : make_float4(0.f, 0.f, 0.f, 0.f);
        sum4.x -= subv.x; sum4.y -= subv.y; sum4.z -= subv.z; sum4.w -= subv.w;

        const float4 tg = t[r * C4 + w];
        const float4 xv = p[r * C4 + w];

        // thread-local inclusive prefix over 4 values
        const float p0 = vs.x;
        const float p1 = p0 + vs.y;
        const float p2 = p1 + vs.z;
        const float p3 = p2 + vs.w;

        // warp scan of thread totals
        const float isc  = warp_iscan(p3, lane);
        const float excl = isc - p3;
        if (lane == 31) s_warp[buf][wid] = isc;
        __syncthreads();

        const float w0 = s_warp[buf][0];
        const float w1 = s_warp[buf][1];
        const float w2 = s_warp[buf][2];
        const float w3 = s_warp[buf][3];
        const float woff = (wid > 0 ? w0 : 0.f) + (wid > 1 ? w1 : 0.f)
                         + (wid > 2 ? w2 : 0.f);
        const float base = woff + excl;

        sP[buf][w + 4] = make_float4(base + p0, base + p1, base + p2, base + p3);
        if (w < 4) {
            const float tot = w0 + w1 + w2 + w3;     // P[511]
            sP[buf][132 + w] = make_float4(tot, tot, tot, tot);
        }
        __syncthreads();

        const float4 lo = sP[buf][w];       // P4[w-4] -> P[4w+k-16]
        const float4 A  = sP[buf][w + 7];   // P4[w+3]
        const float4 Bv = sP[buf][w + 8];   // P4[w+4]

        const float hix = A.w, hiy = Bv.x, hiz = Bv.y, hiw = Bv.z;

        float box[4], tgv[4], x[4];
        box[0] = (hix - lo.x) * inv; box[1] = (hiy - lo.y) * inv;
        box[2] = (hiz - lo.z) * inv; box[3] = (hiw - lo.w) * inv;
        tgv[0] = tg.x; tgv[1] = tg.y; tgv[2] = tg.z; tgv[3] = tg.w;
        x[0] = xv.x; x[1] = xv.y; x[2] = xv.z; x[3] = xv.w;

        #pragma unroll
        for (int k = 0; k < 4; ++k) {
            const float weit = 1.0f + 5.0f * fabsf(box[k] - tgv[k]);
            const float e    = __expf(-fabsf(x[k]));
            const float lg   = __logf(1.0f + e);
            const float bce  = fmaxf(x[k], 0.0f) - x[k] * tgv[k] + lg;
            const float invs = __fdividef(1.0f, 1.0f + e);
            const float pr   = (x[k] >= 0.0f) ? invs : 1.0f - invs;

            acc0 += weit;
            acc1 += weit * bce;
            acc2 += pr * tgv[k] * weit;
            acc3 += (pr + tgv[k]) * weit;
        }
    }

    // ---- block reduction (4 warps) ----
    float vals[4] = {acc0, acc1, acc2, acc3};
    #pragma unroll
    for (int k = 0; k < 4; ++k) {
        const float v = warp_reduce(vals[k]);
        if (lane == 0) s_red[k][wid] = v;
    }
    __syncthreads();

    if (wid == 0) {
        float v[4];
        #pragma unroll
        for (int k = 0; k < 4; ++k) {
            float vv = (lane < 4) ? s_red[k][lane] : 0.f;
            #pragma unroll
            for (int o = 2; o > 0; o >>= 1) vv += __shfl_down_sync(0xffffffffu, vv, o);
            v[k] = vv;
        }
        if (lane == 0) {
            #pragma unroll
            for (int k = 0; k < 4; ++k)
                g_part[(b * STRIPS + strip) * 4 + k] = v[k];
            __threadfence();
        }
        __syncwarp();

        unsigned int ticket = 0;
        if (lane == 0) ticket = atomicAdd(&g_ctr, 1u);
        ticket = __shfl_sync(0xffffffffu, ticket, 0);
        if (ticket == NBLOCKS - 1) {
            // lane = image index (32 lanes, 32 images)
            float wsum = 0.f, wbce_n = 0.f, inter = 0.f, uni = 0.f;
            #pragma unroll 4
            for (int s = 0; s < STRIPS; ++s) {
                const float* pp = &g_part[(lane * STRIPS + s) * 4];
                wsum   += pp[0];
                wbce_n += pp[1];
                inter  += pp[2];
                uni    += pp[3];
            }
            const float wbce = wbce_n / wsum;
            const float wiou = 1.0f - (inter + 1.0f) / (uni - inter + 1.0f);
            float loss = warp_reduce(wbce + wiou);
            if (lane == 0) {
                out[0] = loss * (1.0f / B);
                g_ctr = 0;   // reset for graph replay
            }
        }
    }
}

extern "C" void kernel_launch(void* const* d_in, const int* in_sizes, int n_in,
                              void* d_out, int out_size) {
    const float4* pred   = (const float4*)d_in[0];
    const float4* target = (const float4*)d_in[1];
    float* out = (float*)d_out;

    dim3 grid(STRIPS, B);
    fused_loss_kernel<<<grid, 128>>>(pred, target, out);
}